// round 4
// baseline (speedup 1.0000x reference)
#include <cuda_runtime.h>
#include <cstdint>

// ---------------------------------------------------------------------------
// FlashSVDLlamaBlock: fp32, scratch-minimized (61 MB static, reuse-scheduled)
//   B=2, T=1024, D=2048, H=32, HK=8, DH=64, RQ=RKV=48, RO=RFF=1024, INTER=8192
//
// Scratch regions (floats), with phase-liveness reuse:
//   H [4,194,304]: hbuf (rms1) -> attn -> hbuf (rms2)
//   B [4,718,592]: qr/kr/vr    -> ar   -> gr/ur
//   C [6,291,456]: qb/kb/vb    -> inner_chunk + dr
// inner is processed in 8 chunks of 256 tokens (chunk = 2,097,152 floats),
// so the [2048,8192] activation is never materialized.
// ---------------------------------------------------------------------------

#define NTOK 2048          // B*T
#define DMODEL 2048
#define NH 32
#define NHK 8
#define DHEAD 64
#define RNK 48
#define TSEQ 1024
#define NCHUNK 256         // token chunk for inner

#define OFF_H 0u
#define OFF_B 4194304u
#define OFF_C 8912896u
#define SCRATCH_TOTAL 15204352u   // 61 MB

__device__ float g_scratch[SCRATCH_TOTAL];

// ---------------------------------------------------------------------------
// RMSNorm: one block per token, 256 threads, D=2048
// ---------------------------------------------------------------------------
__global__ void __launch_bounds__(256) rms_kernel(const float* __restrict__ x,
                                                  const float* __restrict__ w,
                                                  float* __restrict__ out) {
    int n = blockIdx.x;
    int tid = threadIdx.x;
    const float4* xr = (const float4*)(x + (size_t)n * DMODEL);
    float4 loc[2];
    float ss = 0.f;
#pragma unroll
    for (int i = 0; i < 2; i++) {
        float4 v = xr[tid + i * 256];
        loc[i] = v;
        ss += v.x * v.x + v.y * v.y + v.z * v.z + v.w * v.w;
    }
#pragma unroll
    for (int off = 16; off; off >>= 1)
        ss += __shfl_xor_sync(0xffffffffu, ss, off);
    __shared__ float red[8];
    if ((tid & 31) == 0) red[tid >> 5] = ss;
    __syncthreads();
    float tot = red[0] + red[1] + red[2] + red[3] + red[4] + red[5] + red[6] + red[7];
    float inv = rsqrtf(tot * (1.0f / (float)DMODEL) + 1e-5f);
    const float4* w4 = (const float4*)w;
    float4* o4 = (float4*)(out + (size_t)n * DMODEL);
#pragma unroll
    for (int i = 0; i < 2; i++) {
        int idx = tid + i * 256;
        float4 wv = w4[idx];
        float4 v = loc[i];
        o4[idx] = make_float4(v.x * inv * wv.x, v.y * inv * wv.y,
                              v.z * inv * wv.z, v.w * inv * wv.w);
    }
}

// ---------------------------------------------------------------------------
// Generic SGEMM:  C[n,m] = sum_k A[n,k] * W[m,k]
//   MODE 0: C = acc;  MODE 1: C = acc + R[n,m];  MODE 2: C += acc
// Block tile 64x64, BK=16, 256 threads, 4x4 per thread.
// A rows are offset by n_base (for chunked launches).
// ---------------------------------------------------------------------------
template <int MODE>
__global__ void __launch_bounds__(256) gemm_nt(const float* __restrict__ A,
                                               const float* __restrict__ W,
                                               const float* __restrict__ R,
                                               float* __restrict__ C,
                                               int M, int K) {
    __shared__ float As[16][68];
    __shared__ float Ws[16][68];
    int n0 = blockIdx.y * 64;
    int m0 = blockIdx.x * 64;
    int tid = threadIdx.x;
    int tx = tid & 15;       // col group
    int ty = tid >> 4;       // row group
    int arow = tid >> 2;     // 0..63
    int acol = (tid & 3) * 4;
    const float* Ap = A + (size_t)(n0 + arow) * K + acol;
    const float* Wp = W + (size_t)(m0 + arow) * K + acol;
    float acc[4][4] = {};
    for (int k0 = 0; k0 < K; k0 += 16) {
        float4 av = *(const float4*)(Ap + k0);
        float4 wv = *(const float4*)(Wp + k0);
        __syncthreads();
        As[acol + 0][arow] = av.x; As[acol + 1][arow] = av.y;
        As[acol + 2][arow] = av.z; As[acol + 3][arow] = av.w;
        Ws[acol + 0][arow] = wv.x; Ws[acol + 1][arow] = wv.y;
        Ws[acol + 2][arow] = wv.z; Ws[acol + 3][arow] = wv.w;
        __syncthreads();
#pragma unroll
        for (int k = 0; k < 16; k++) {
            float ra[4], rw[4];
#pragma unroll
            for (int i = 0; i < 4; i++) {
                ra[i] = As[k][ty * 4 + i];
                rw[i] = Ws[k][tx * 4 + i];
            }
#pragma unroll
            for (int i = 0; i < 4; i++)
#pragma unroll
                for (int j = 0; j < 4; j++)
                    acc[i][j] += ra[i] * rw[j];
        }
    }
#pragma unroll
    for (int i = 0; i < 4; i++) {
        int n = n0 + ty * 4 + i;
#pragma unroll
        for (int j = 0; j < 4; j++) {
            int m = m0 + tx * 4 + j;
            float v = acc[i][j];
            if (MODE == 1) v += R[(size_t)n * M + m];
            if (MODE == 2) v += C[(size_t)n * M + m];
            C[(size_t)n * M + m] = v;
        }
    }
}

// ---------------------------------------------------------------------------
// Fused gate/up GEMM + SiLU (chunk of N rows):
//   inner[n,m] = silu(Ag[n,:]·Wg[m,:]) * (Au[n,:]·Wu[m,:])    (K=1024, M=8192)
// ---------------------------------------------------------------------------
__global__ void __launch_bounds__(256) gateup_kernel(const float* __restrict__ Ag,
                                                     const float* __restrict__ Au,
                                                     const float* __restrict__ Wg,
                                                     const float* __restrict__ Wu,
                                                     float* __restrict__ C,
                                                     int M, int K) {
    __shared__ float Ags[16][68];
    __shared__ float Aus[16][68];
    __shared__ float Wgs[16][68];
    __shared__ float Wus[16][68];
    int n0 = blockIdx.y * 64;
    int m0 = blockIdx.x * 64;
    int tid = threadIdx.x;
    int tx = tid & 15;
    int ty = tid >> 4;
    int arow = tid >> 2;
    int acol = (tid & 3) * 4;
    const float* Agp = Ag + (size_t)(n0 + arow) * K + acol;
    const float* Aup = Au + (size_t)(n0 + arow) * K + acol;
    const float* Wgp = Wg + (size_t)(m0 + arow) * K + acol;
    const float* Wup = Wu + (size_t)(m0 + arow) * K + acol;
    float accg[4][4] = {};
    float accu[4][4] = {};
    for (int k0 = 0; k0 < K; k0 += 16) {
        float4 ag = *(const float4*)(Agp + k0);
        float4 au = *(const float4*)(Aup + k0);
        float4 wg = *(const float4*)(Wgp + k0);
        float4 wu = *(const float4*)(Wup + k0);
        __syncthreads();
        Ags[acol + 0][arow] = ag.x; Ags[acol + 1][arow] = ag.y;
        Ags[acol + 2][arow] = ag.z; Ags[acol + 3][arow] = ag.w;
        Aus[acol + 0][arow] = au.x; Aus[acol + 1][arow] = au.y;
        Aus[acol + 2][arow] = au.z; Aus[acol + 3][arow] = au.w;
        Wgs[acol + 0][arow] = wg.x; Wgs[acol + 1][arow] = wg.y;
        Wgs[acol + 2][arow] = wg.z; Wgs[acol + 3][arow] = wg.w;
        Wus[acol + 0][arow] = wu.x; Wus[acol + 1][arow] = wu.y;
        Wus[acol + 2][arow] = wu.z; Wus[acol + 3][arow] = wu.w;
        __syncthreads();
#pragma unroll
        for (int k = 0; k < 16; k++) {
            float rag[4], rau[4], rwg[4], rwu[4];
#pragma unroll
            for (int i = 0; i < 4; i++) {
                rag[i] = Ags[k][ty * 4 + i];
                rau[i] = Aus[k][ty * 4 + i];
                rwg[i] = Wgs[k][tx * 4 + i];
                rwu[i] = Wus[k][tx * 4 + i];
            }
#pragma unroll
            for (int i = 0; i < 4; i++)
#pragma unroll
                for (int j = 0; j < 4; j++) {
                    accg[i][j] += rag[i] * rwg[j];
                    accu[i][j] += rau[i] * rwu[j];
                }
        }
    }
#pragma unroll
    for (int i = 0; i < 4; i++) {
        int n = n0 + ty * 4 + i;
#pragma unroll
        for (int j = 0; j < 4; j++) {
            int m = m0 + tx * 4 + j;
            float g = accg[i][j];
            float u = accu[i][j];
            float silu = g / (1.0f + expf(-g));
            C[(size_t)n * M + m] = silu * u;
        }
    }
}

// ---------------------------------------------------------------------------
// Per-head Us projection (+ optional RoPE, interleaved-frequency variant):
//   out[b,h,t,dh] = sum_r Rv[n, h*48+r] * Us[h, dh, r]   then RoPE
// One block per (t, h, b), 64 threads (one per dh).
// ---------------------------------------------------------------------------
__global__ void __launch_bounds__(64) proj_kernel(const float* __restrict__ Rv,
                                                  const float* __restrict__ Us,
                                                  const int* __restrict__ pos_ids,
                                                  float* __restrict__ out,
                                                  int nheads, int do_rope) {
    int t = blockIdx.x;
    int h = blockIdx.y;
    int b = blockIdx.z;
    int n = b * TSEQ + t;
    int dh = threadIdx.x;
    __shared__ float rv[RNK];
    __shared__ float raw[DHEAD];
    if (dh < RNK) rv[dh] = Rv[(size_t)n * (nheads * RNK) + h * RNK + dh];
    __syncthreads();
    const float* us = Us + ((size_t)h * DHEAD + dh) * RNK;
    float acc = 0.f;
#pragma unroll
    for (int r = 0; r < RNK; r++) acc += us[r] * rv[r];
    float val = acc;
    if (do_rope) {
        raw[dh] = acc;
        __syncthreads();
        float pos = (float)pos_ids[t];
        int fi = dh >> 1;                       // inv_freq index 0..31
        float inv = expf(-(float)fi * (9.210340371976184f / 32.0f));
        float ang = pos * inv;
        float c = cosf(ang);
        float s = sinf(ang);
        float partner = (dh < 32) ? -raw[dh + 32] : raw[dh - 32];
        val = acc * c + partner * s;
    }
    out[(((size_t)b * nheads + h) * TSEQ + t) * DHEAD + dh] = val;
}

// ---------------------------------------------------------------------------
// Causal flash attention, fp32. One query per thread, 128 queries per block.
// K/V tiles (32x64) in smem, broadcast reads. GQA: hk = h/4.
// Output layout: attn[b, t, h*64 + d]  (== transpose+reshape in reference)
// ---------------------------------------------------------------------------
__global__ void __launch_bounds__(128) flash_kernel(const float* __restrict__ Q,
                                                    const float* __restrict__ Kg,
                                                    const float* __restrict__ Vg,
                                                    float* __restrict__ Out) {
    int bh = blockIdx.y;
    int b = bh >> 5;
    int h = bh & 31;
    int hk = h >> 2;
    int q0 = blockIdx.x * 128;
    int tid = threadIdx.x;
    int qi = q0 + tid;

    __shared__ float Ks[32][64];
    __shared__ float Vs[32][64];

    float qreg[64];
    const float* qp = Q + (((size_t)b * NH + h) * TSEQ + qi) * DHEAD;
#pragma unroll
    for (int d4 = 0; d4 < 16; d4++) {
        float4 v = *(const float4*)(qp + d4 * 4);
        qreg[d4 * 4 + 0] = v.x; qreg[d4 * 4 + 1] = v.y;
        qreg[d4 * 4 + 2] = v.z; qreg[d4 * 4 + 3] = v.w;
    }
    float m = -1e30f, l = 0.f;
    float o[64];
#pragma unroll
    for (int d = 0; d < 64; d++) o[d] = 0.f;

    const float* kbase = Kg + (((size_t)b * NHK + hk) * TSEQ) * DHEAD;
    const float* vbase = Vg + (((size_t)b * NHK + hk) * TSEQ) * DHEAD;
    int nkt = (q0 + 128) / 32;   // causal bound: keys 0 .. q0+127

    for (int kt = 0; kt < nkt; kt++) {
        int kstart = kt * 32;
        __syncthreads();
#pragma unroll
        for (int i = 0; i < 4; i++) {
            int e = tid + i * 128;          // float4 index 0..511
            int row = e >> 4;
            int col = (e & 15) * 4;
            *(float4*)&Ks[row][col] = *(const float4*)(kbase + (size_t)(kstart + row) * 64 + col);
            *(float4*)&Vs[row][col] = *(const float4*)(vbase + (size_t)(kstart + row) * 64 + col);
        }
        __syncthreads();

        float s[32];
#pragma unroll
        for (int j = 0; j < 32; j++) {
            float acc = 0.f;
#pragma unroll
            for (int d4 = 0; d4 < 16; d4++) {
                float4 kv = *(const float4*)&Ks[j][d4 * 4];
                acc += qreg[d4 * 4 + 0] * kv.x + qreg[d4 * 4 + 1] * kv.y +
                       qreg[d4 * 4 + 2] * kv.z + qreg[d4 * 4 + 3] * kv.w;
            }
            s[j] = (kstart + j <= qi) ? acc * 0.125f : -1e30f;
        }
        float mt = m;
#pragma unroll
        for (int j = 0; j < 32; j++) mt = fmaxf(mt, s[j]);
        float corr = expf(m - mt);
        m = mt;
        l *= corr;
#pragma unroll
        for (int d = 0; d < 64; d++) o[d] *= corr;
#pragma unroll
        for (int j = 0; j < 32; j++) {
            float p = expf(s[j] - m);
            l += p;
#pragma unroll
            for (int d4 = 0; d4 < 16; d4++) {
                float4 vv = *(const float4*)&Vs[j][d4 * 4];
                o[d4 * 4 + 0] += p * vv.x; o[d4 * 4 + 1] += p * vv.y;
                o[d4 * 4 + 2] += p * vv.z; o[d4 * 4 + 3] += p * vv.w;
            }
        }
    }
    float invl = 1.0f / l;
    float* op = Out + ((size_t)b * TSEQ + qi) * DMODEL + h * DHEAD;
#pragma unroll
    for (int d = 0; d < 64; d++) op[d] = o[d] * invl;
}

// ---------------------------------------------------------------------------
// Launch (with phase-liveness buffer reuse; see header comment)
// ---------------------------------------------------------------------------
extern "C" void kernel_launch(void* const* d_in, const int* in_sizes, int n_in,
                              void* d_out, int out_size) {
    const float* x     = (const float*)d_in[0];
    const int*   pos   = (const int*)d_in[1];
    const float* ln1   = (const float*)d_in[2];
    const float* ln2   = (const float*)d_in[3];
    const float* q_Us  = (const float*)d_in[4];
    const float* q_V   = (const float*)d_in[5];
    const float* k_Us  = (const float*)d_in[6];
    const float* k_V   = (const float*)d_in[7];
    const float* v_Us  = (const float*)d_in[8];
    const float* v_V   = (const float*)d_in[9];
    const float* o_Us  = (const float*)d_in[10];
    const float* o_V   = (const float*)d_in[11];
    const float* g_Us  = (const float*)d_in[12];
    const float* g_V   = (const float*)d_in[13];
    const float* u_Us  = (const float*)d_in[14];
    const float* u_V   = (const float*)d_in[15];
    const float* d_Us  = (const float*)d_in[16];
    const float* d_V   = (const float*)d_in[17];
    float* out = (float*)d_out;

    float* S = nullptr;
    cudaGetSymbolAddress((void**)&S, g_scratch);
    float* H = S + OFF_H;          // 4,194,304 floats
    float* Bb = S + OFF_B;         // 4,718,592 floats
    float* C = S + OFF_C;          // 6,291,456 floats

    // aliases by phase
    float* hbuf  = H;
    float* qr    = Bb;                       // 2048*1536
    float* kr    = Bb + 3145728;             // 2048*384
    float* vr    = Bb + 3932160;             // 2048*384
    float* qb    = C;                        // 2*32*1024*64
    float* kb    = C + 4194304;              // 2*8*1024*64
    float* vb    = C + 5242880;              // 2*8*1024*64
    float* attn  = H;                        // 2048*2048 (hbuf dead)
    float* ar    = Bb;                       // 2048*1024 (qr/kr/vr dead)
    float* gr    = Bb;                       // 2048*1024 (ar dead)
    float* ur    = Bb + 2097152;             // 2048*1024
    float* dr    = C + 2097152;              // 2048*1024 (qb/kb/vb dead)
    // inner chunk: C + 0 .. 2,097,151  (256*8192 per chunk)

    // ---- attention sub-block ----
    rms_kernel<<<NTOK, 256>>>(x, ln1, hbuf);
    gemm_nt<0><<<dim3(24, 32), 256>>>(hbuf, q_V, nullptr, qr, 1536, 2048);
    gemm_nt<0><<<dim3(6, 32), 256>>>(hbuf, k_V, nullptr, kr, 384, 2048);
    gemm_nt<0><<<dim3(6, 32), 256>>>(hbuf, v_V, nullptr, vr, 384, 2048);
    proj_kernel<<<dim3(TSEQ, NH, 2), 64>>>(qr, q_Us, pos, qb, NH, 1);
    proj_kernel<<<dim3(TSEQ, NHK, 2), 64>>>(kr, k_Us, pos, kb, NHK, 1);
    proj_kernel<<<dim3(TSEQ, NHK, 2), 64>>>(vr, v_Us, pos, vb, NHK, 0);
    flash_kernel<<<dim3(8, 64), 128>>>(qb, kb, vb, attn);
    gemm_nt<0><<<dim3(16, 32), 256>>>(attn, o_V, nullptr, ar, 1024, 2048);
    gemm_nt<1><<<dim3(32, 32), 256>>>(ar, o_Us, x, out, 2048, 1024);

    // ---- MLP sub-block ----
    rms_kernel<<<NTOK, 256>>>(out, ln2, hbuf);                  // attn dead -> H reused
    gemm_nt<0><<<dim3(16, 32), 256>>>(hbuf, g_V, nullptr, gr, 1024, 2048);
    gemm_nt<0><<<dim3(16, 32), 256>>>(hbuf, u_V, nullptr, ur, 1024, 2048);

    // chunked inner: 8 chunks of 256 tokens; inner_chunk lives in C[0..2,097,151]
    for (int c = 0; c < NTOK / NCHUNK; c++) {
        const float* grc = gr + (size_t)c * NCHUNK * 1024;
        const float* urc = ur + (size_t)c * NCHUNK * 1024;
        float* innerc = C;                              // 256 x 8192
        float* drc = dr + (size_t)c * NCHUNK * 1024;    // 256 x 1024
        gateup_kernel<<<dim3(128, NCHUNK / 64), 256>>>(grc, urc, g_Us, u_Us,
                                                       innerc, 8192, 1024);
        gemm_nt<0><<<dim3(16, NCHUNK / 64), 256>>>(innerc, d_V, nullptr, drc,
                                                   1024, 8192);
    }
    gemm_nt<2><<<dim3(32, 32), 256>>>(dr, d_Us, nullptr, out, 2048, 1024);
}

// round 5
// speedup vs baseline: 1.8355x; 1.8355x over previous
#include <cuda_runtime.h>
#include <cstdint>

// ---------------------------------------------------------------------------
// FlashSVDLlamaBlock R5: packed-f32x2 SGEMM (128x128x8 double-buffered),
// qkv-weight concat, 512-token MLP chunks, split-K d_V.
//   B=2, T=1024, D=2048, H=32, HK=8, DH=64, R=48, RO=RFF=1024, INTER=8192
// Scratch (61 MB, contiguous, phase-liveness reuse):
//   H [0      .. 4,194,303]: hbuf -> attn -> hbuf -> dr
//   B [4,194,304 .. 8,912,895]: qkvr -> ar -> gr/ur
//   C [8,912,896 .. 15,204,351]: wconcat -> qb/kb/vb -> inner + partials
// ---------------------------------------------------------------------------

#define NTOK 2048
#define DMODEL 2048
#define NH 32
#define NHK 8
#define DHEAD 64
#define RNK 48
#define TSEQ 1024
#define NCHUNK 512

#define OFF_H 0u
#define OFF_B 4194304u
#define OFF_C 8912896u
#define SCRATCH_TOTAL 15204352u

__device__ float g_scratch[SCRATCH_TOTAL];

// ---- packed f32x2 helpers --------------------------------------------------
__device__ __forceinline__ unsigned long long pk2(float v) {
    unsigned long long r;
    asm("mov.b64 %0, {%1, %1};" : "=l"(r) : "f"(v));
    return r;
}
__device__ __forceinline__ void fma2(unsigned long long& c, unsigned long long a,
                                     unsigned long long b) {
    asm("fma.rn.f32x2 %0, %1, %2, %0;" : "+l"(c) : "l"(a), "l"(b));
}
__device__ __forceinline__ float2 upk2(unsigned long long v) {
    float2 r;
    asm("mov.b64 {%0, %1}, %2;" : "=f"(r.x), "=f"(r.y) : "l"(v));
    return r;
}

// ---------------------------------------------------------------------------
// RMSNorm
// ---------------------------------------------------------------------------
__global__ void __launch_bounds__(256) rms_kernel(const float* __restrict__ x,
                                                  const float* __restrict__ w,
                                                  float* __restrict__ out) {
    int n = blockIdx.x;
    int tid = threadIdx.x;
    const float4* xr = (const float4*)(x + (size_t)n * DMODEL);
    float4 loc[2];
    float ss = 0.f;
#pragma unroll
    for (int i = 0; i < 2; i++) {
        float4 v = xr[tid + i * 256];
        loc[i] = v;
        ss += v.x * v.x + v.y * v.y + v.z * v.z + v.w * v.w;
    }
#pragma unroll
    for (int off = 16; off; off >>= 1)
        ss += __shfl_xor_sync(0xffffffffu, ss, off);
    __shared__ float red[8];
    if ((tid & 31) == 0) red[tid >> 5] = ss;
    __syncthreads();
    float tot = red[0] + red[1] + red[2] + red[3] + red[4] + red[5] + red[6] + red[7];
    float inv = rsqrtf(tot * (1.0f / (float)DMODEL) + 1e-5f);
    const float4* w4 = (const float4*)w;
    float4* o4 = (float4*)(out + (size_t)n * DMODEL);
#pragma unroll
    for (int i = 0; i < 2; i++) {
        int idx = tid + i * 256;
        float4 wv = w4[idx];
        float4 v = loc[i];
        o4[idx] = make_float4(v.x * inv * wv.x, v.y * inv * wv.y,
                              v.z * inv * wv.z, v.w * inv * wv.w);
    }
}

// ---------------------------------------------------------------------------
// SGEMM 128x128, BK=8, 256 thr, 8x8 micro via f32x2, double-buffered.
//   C[n,m] = sum_k A[n,k]*W[m,k];  MODE 0: =, 1: +R, 2: +=C
// Split-K: blockIdx.z selects K-range [z*Kt,(z+1)*Kt), output rows offset by
// z*gridDim.y*128 (partial-sum layout). Non-split: gridDim.z=1, Kt=K.
// ---------------------------------------------------------------------------
template <int MODE>
__global__ void __launch_bounds__(256, 2) gemm128(const float* __restrict__ A,
                                                  const float* __restrict__ W,
                                                  const float* __restrict__ R,
                                                  float* __restrict__ C,
                                                  int M, int K, int Kt) {
    __shared__ __align__(16) float As[2][8][128];
    __shared__ __align__(16) float Ws[2][8][128];
    int n0 = blockIdx.y * 128, m0 = blockIdx.x * 128;
    int tid = threadIdx.x;
    int tx = tid & 15, ty = tid >> 4;
    int lrow = tid >> 1;
    int lcol = (tid & 1) * 4;
    size_t koff = (size_t)blockIdx.z * Kt;
    const float* Ap = A + (size_t)(n0 + lrow) * K + koff + lcol;
    const float* Wp = W + (size_t)(m0 + lrow) * K + koff + lcol;

    unsigned long long acc[8][4];
#pragma unroll
    for (int i = 0; i < 8; i++)
#pragma unroll
        for (int j = 0; j < 4; j++) acc[i][j] = 0ull;

    int nt = Kt >> 3;
    float4 av = *(const float4*)Ap;
    float4 wv = *(const float4*)Wp;
    As[0][lcol + 0][lrow] = av.x; As[0][lcol + 1][lrow] = av.y;
    As[0][lcol + 2][lrow] = av.z; As[0][lcol + 3][lrow] = av.w;
    Ws[0][lcol + 0][lrow] = wv.x; Ws[0][lcol + 1][lrow] = wv.y;
    Ws[0][lcol + 2][lrow] = wv.z; Ws[0][lcol + 3][lrow] = wv.w;
    __syncthreads();

    for (int kt = 0; kt < nt; kt++) {
        int cur = kt & 1;
        float4 av2, wv2;
        bool has = (kt + 1 < nt);
        if (has) {
            av2 = *(const float4*)(Ap + (size_t)(kt + 1) * 8);
            wv2 = *(const float4*)(Wp + (size_t)(kt + 1) * 8);
        }
#pragma unroll
        for (int k = 0; k < 8; k++) {
            float4 a0 = *(const float4*)&As[cur][k][ty * 4];
            float4 a1 = *(const float4*)&As[cur][k][64 + ty * 4];
            ulonglong2 w0 = *(const ulonglong2*)&Ws[cur][k][tx * 4];
            ulonglong2 w1 = *(const ulonglong2*)&Ws[cur][k][64 + tx * 4];
#define GROW(i, aval)                                   \
            {                                           \
                unsigned long long ap = pk2(aval);      \
                fma2(acc[i][0], ap, w0.x);              \
                fma2(acc[i][1], ap, w0.y);              \
                fma2(acc[i][2], ap, w1.x);              \
                fma2(acc[i][3], ap, w1.y);              \
            }
            GROW(0, a0.x) GROW(1, a0.y) GROW(2, a0.z) GROW(3, a0.w)
            GROW(4, a1.x) GROW(5, a1.y) GROW(6, a1.z) GROW(7, a1.w)
#undef GROW
        }
        if (has) {
            int nxt = cur ^ 1;
            As[nxt][lcol + 0][lrow] = av2.x; As[nxt][lcol + 1][lrow] = av2.y;
            As[nxt][lcol + 2][lrow] = av2.z; As[nxt][lcol + 3][lrow] = av2.w;
            Ws[nxt][lcol + 0][lrow] = wv2.x; Ws[nxt][lcol + 1][lrow] = wv2.y;
            Ws[nxt][lcol + 2][lrow] = wv2.z; Ws[nxt][lcol + 3][lrow] = wv2.w;
            __syncthreads();
        }
    }

    int zrow = blockIdx.z * (gridDim.y << 7);
#pragma unroll
    for (int i = 0; i < 8; i++) {
        int n = n0 + (i >> 2) * 64 + ty * 4 + (i & 3);
        size_t base = (size_t)(zrow + n) * M;
        float2 p0 = upk2(acc[i][0]), p1 = upk2(acc[i][1]);
        float2 p2 = upk2(acc[i][2]), p3 = upk2(acc[i][3]);
        float4 lo = make_float4(p0.x, p0.y, p1.x, p1.y);
        float4 hi = make_float4(p2.x, p2.y, p3.x, p3.y);
        float* clo = &C[base + m0 + tx * 4];
        float* chi = &C[base + m0 + 64 + tx * 4];
        if (MODE == 1) {
            const float4 rlo = *(const float4*)&R[base + m0 + tx * 4];
            const float4 rhi = *(const float4*)&R[base + m0 + 64 + tx * 4];
            lo.x += rlo.x; lo.y += rlo.y; lo.z += rlo.z; lo.w += rlo.w;
            hi.x += rhi.x; hi.y += rhi.y; hi.z += rhi.z; hi.w += rhi.w;
        }
        if (MODE == 2) {
            const float4 rlo = *(const float4*)clo;
            const float4 rhi = *(const float4*)chi;
            lo.x += rlo.x; lo.y += rlo.y; lo.z += rlo.z; lo.w += rlo.w;
            hi.x += rhi.x; hi.y += rhi.y; hi.z += rhi.z; hi.w += rhi.w;
        }
        *(float4*)clo = lo;
        *(float4*)chi = hi;
    }
}

// ---------------------------------------------------------------------------
// Fused gate/up GEMM + SiLU, 128(N)x64(M), BK=8, 8x4 micro via f32x2.
//   inner[n,m] = silu(Ag·Wg) * (Au·Wu);  K=1024, M=8192
// ---------------------------------------------------------------------------
__global__ void __launch_bounds__(256, 2) gateup_kernel(const float* __restrict__ Ag,
                                                        const float* __restrict__ Au,
                                                        const float* __restrict__ Wg,
                                                        const float* __restrict__ Wu,
                                                        float* __restrict__ C,
                                                        int M, int K) {
    __shared__ __align__(16) float Ags[2][8][128];
    __shared__ __align__(16) float Aus[2][8][128];
    __shared__ __align__(16) float Wgs[2][8][64];
    __shared__ __align__(16) float Wus[2][8][64];
    int n0 = blockIdx.y * 128, m0 = blockIdx.x * 64;
    int tid = threadIdx.x;
    int tx = tid & 15, ty = tid >> 4;
    int lrow = tid >> 1;
    int lcol = (tid & 1) * 4;
    int wrow = (tid & 127) >> 1;
    int wcol = (tid & 1) * 4;
    bool isg = tid < 128;
    const float* Agp = Ag + (size_t)(n0 + lrow) * K + lcol;
    const float* Aup = Au + (size_t)(n0 + lrow) * K + lcol;
    const float* Wp = (isg ? Wg : Wu) + (size_t)(m0 + wrow) * K + wcol;

    unsigned long long accg[8][2], accu[8][2];
#pragma unroll
    for (int i = 0; i < 8; i++) {
        accg[i][0] = accg[i][1] = 0ull;
        accu[i][0] = accu[i][1] = 0ull;
    }

    int nt = K >> 3;
    float4 ag = *(const float4*)Agp;
    float4 au = *(const float4*)Aup;
    float4 wv = *(const float4*)Wp;
    Ags[0][lcol + 0][lrow] = ag.x; Ags[0][lcol + 1][lrow] = ag.y;
    Ags[0][lcol + 2][lrow] = ag.z; Ags[0][lcol + 3][lrow] = ag.w;
    Aus[0][lcol + 0][lrow] = au.x; Aus[0][lcol + 1][lrow] = au.y;
    Aus[0][lcol + 2][lrow] = au.z; Aus[0][lcol + 3][lrow] = au.w;
    {
        float* ws = isg ? &Wgs[0][0][0] : &Wus[0][0][0];
        ws[(wcol + 0) * 64 + wrow] = wv.x; ws[(wcol + 1) * 64 + wrow] = wv.y;
        ws[(wcol + 2) * 64 + wrow] = wv.z; ws[(wcol + 3) * 64 + wrow] = wv.w;
    }
    __syncthreads();

    for (int kt = 0; kt < nt; kt++) {
        int cur = kt & 1;
        float4 ag2, au2, wv2;
        bool has = (kt + 1 < nt);
        if (has) {
            ag2 = *(const float4*)(Agp + (size_t)(kt + 1) * 8);
            au2 = *(const float4*)(Aup + (size_t)(kt + 1) * 8);
            wv2 = *(const float4*)(Wp + (size_t)(kt + 1) * 8);
        }
#pragma unroll
        for (int k = 0; k < 8; k++) {
            float4 g0 = *(const float4*)&Ags[cur][k][ty * 4];
            float4 g1 = *(const float4*)&Ags[cur][k][64 + ty * 4];
            float4 u0 = *(const float4*)&Aus[cur][k][ty * 4];
            float4 u1 = *(const float4*)&Aus[cur][k][64 + ty * 4];
            ulonglong2 wg = *(const ulonglong2*)&Wgs[cur][k][tx * 4];
            ulonglong2 wu = *(const ulonglong2*)&Wus[cur][k][tx * 4];
#define GUROW(i, gv, uv)                                  \
            {                                             \
                unsigned long long apg = pk2(gv);         \
                unsigned long long apu = pk2(uv);         \
                fma2(accg[i][0], apg, wg.x);              \
                fma2(accg[i][1], apg, wg.y);              \
                fma2(accu[i][0], apu, wu.x);              \
                fma2(accu[i][1], apu, wu.y);              \
            }
            GUROW(0, g0.x, u0.x) GUROW(1, g0.y, u0.y)
            GUROW(2, g0.z, u0.z) GUROW(3, g0.w, u0.w)
            GUROW(4, g1.x, u1.x) GUROW(5, g1.y, u1.y)
            GUROW(6, g1.z, u1.z) GUROW(7, g1.w, u1.w)
#undef GUROW
        }
        if (has) {
            int nxt = cur ^ 1;
            Ags[nxt][lcol + 0][lrow] = ag2.x; Ags[nxt][lcol + 1][lrow] = ag2.y;
            Ags[nxt][lcol + 2][lrow] = ag2.z; Ags[nxt][lcol + 3][lrow] = ag2.w;
            Aus[nxt][lcol + 0][lrow] = au2.x; Aus[nxt][lcol + 1][lrow] = au2.y;
            Aus[nxt][lcol + 2][lrow] = au2.z; Aus[nxt][lcol + 3][lrow] = au2.w;
            float* ws = isg ? &Wgs[nxt][0][0] : &Wus[nxt][0][0];
            ws[(wcol + 0) * 64 + wrow] = wv2.x; ws[(wcol + 1) * 64 + wrow] = wv2.y;
            ws[(wcol + 2) * 64 + wrow] = wv2.z; ws[(wcol + 3) * 64 + wrow] = wv2.w;
            __syncthreads();
        }
    }

#pragma unroll
    for (int i = 0; i < 8; i++) {
        int n = n0 + (i >> 2) * 64 + ty * 4 + (i & 3);
        float2 gp0 = upk2(accg[i][0]), gp1 = upk2(accg[i][1]);
        float2 up0 = upk2(accu[i][0]), up1 = upk2(accu[i][1]);
        float g[4] = {gp0.x, gp0.y, gp1.x, gp1.y};
        float u[4] = {up0.x, up0.y, up1.x, up1.y};
        float o[4];
#pragma unroll
        for (int j = 0; j < 4; j++) o[j] = (g[j] / (1.0f + expf(-g[j]))) * u[j];
        *(float4*)&C[(size_t)n * M + m0 + tx * 4] = make_float4(o[0], o[1], o[2], o[3]);
    }
}

// ---------------------------------------------------------------------------
// qkv weight concat: wc = [q_V(1536x2048); k_V(384x2048); v_V(384x2048)]
// ---------------------------------------------------------------------------
__global__ void __launch_bounds__(256) concat_qkv(const float* __restrict__ q,
                                                  const float* __restrict__ k,
                                                  const float* __restrict__ v,
                                                  float* __restrict__ wc) {
    int i = blockIdx.x * 256 + threadIdx.x;    // float4 index, total 1,179,648
    float4 val;
    if (i < 786432) val = ((const float4*)q)[i];
    else if (i < 983040) val = ((const float4*)k)[i - 786432];
    else val = ((const float4*)v)[i - 983040];
    ((float4*)wc)[i] = val;
}

// ---------------------------------------------------------------------------
// split-K reduce: dst[i] = sum_{p<4} part[p*524288 + i]   (512x1024 floats)
// ---------------------------------------------------------------------------
__global__ void __launch_bounds__(256) reduce4_kernel(const float* __restrict__ part,
                                                      float* __restrict__ dst) {
    int i = blockIdx.x * 256 + threadIdx.x;    // float4 index, total 131072
    const float4* p = (const float4*)part;
    float4 a = p[i], b = p[i + 131072], c = p[i + 262144], d = p[i + 393216];
    ((float4*)dst)[i] = make_float4(a.x + b.x + c.x + d.x, a.y + b.y + c.y + d.y,
                                    a.z + b.z + c.z + d.z, a.w + b.w + c.w + d.w);
}

// ---------------------------------------------------------------------------
// Per-head Us projection (+ optional RoPE). Rv has row stride `stride`,
// head block at `off`.
// ---------------------------------------------------------------------------
__global__ void __launch_bounds__(64) proj_kernel(const float* __restrict__ Rv,
                                                  const float* __restrict__ Us,
                                                  const int* __restrict__ pos_ids,
                                                  float* __restrict__ out,
                                                  int nheads, int do_rope,
                                                  int stride, int off) {
    int t = blockIdx.x;
    int h = blockIdx.y;
    int b = blockIdx.z;
    int n = b * TSEQ + t;
    int dh = threadIdx.x;
    __shared__ float rv[RNK];
    __shared__ float raw[DHEAD];
    if (dh < RNK) rv[dh] = Rv[(size_t)n * stride + off + h * RNK + dh];
    __syncthreads();
    const float* us = Us + ((size_t)h * DHEAD + dh) * RNK;
    float acc = 0.f;
#pragma unroll
    for (int r = 0; r < RNK; r++) acc += us[r] * rv[r];
    float val = acc;
    if (do_rope) {
        raw[dh] = acc;
        __syncthreads();
        float pos = (float)pos_ids[t];
        int fi = dh >> 1;
        float inv = expf(-(float)fi * (9.210340371976184f / 32.0f));
        float ang = pos * inv;
        float c = cosf(ang);
        float s = sinf(ang);
        float partner = (dh < 32) ? -raw[dh + 32] : raw[dh - 32];
        val = acc * c + partner * s;
    }
    out[(((size_t)b * nheads + h) * TSEQ + t) * DHEAD + dh] = val;
}

// ---------------------------------------------------------------------------
// Causal flash attention, fp32. One query/thread, 128 q/block. GQA hk=h/4.
// Output layout: attn[b, t, h*64 + d]
// ---------------------------------------------------------------------------
__global__ void __launch_bounds__(128) flash_kernel(const float* __restrict__ Q,
                                                    const float* __restrict__ Kg,
                                                    const float* __restrict__ Vg,
                                                    float* __restrict__ Out) {
    int bh = blockIdx.y;
    int b = bh >> 5;
    int h = bh & 31;
    int hk = h >> 2;
    int q0 = blockIdx.x * 128;
    int tid = threadIdx.x;
    int qi = q0 + tid;

    __shared__ float Ks[32][64];
    __shared__ float Vs[32][64];

    float qreg[64];
    const float* qp = Q + (((size_t)b * NH + h) * TSEQ + qi) * DHEAD;
#pragma unroll
    for (int d4 = 0; d4 < 16; d4++) {
        float4 v = *(const float4*)(qp + d4 * 4);
        qreg[d4 * 4 + 0] = v.x; qreg[d4 * 4 + 1] = v.y;
        qreg[d4 * 4 + 2] = v.z; qreg[d4 * 4 + 3] = v.w;
    }
    float m = -1e30f, l = 0.f;
    float o[64];
#pragma unroll
    for (int d = 0; d < 64; d++) o[d] = 0.f;

    const float* kbase = Kg + (((size_t)b * NHK + hk) * TSEQ) * DHEAD;
    const float* vbase = Vg + (((size_t)b * NHK + hk) * TSEQ) * DHEAD;
    int nkt = (q0 + 128) / 32;

    for (int kt = 0; kt < nkt; kt++) {
        int kstart = kt * 32;
        __syncthreads();
#pragma unroll
        for (int i = 0; i < 4; i++) {
            int e = tid + i * 128;
            int row = e >> 4;
            int col = (e & 15) * 4;
            *(float4*)&Ks[row][col] = *(const float4*)(kbase + (size_t)(kstart + row) * 64 + col);
            *(float4*)&Vs[row][col] = *(const float4*)(vbase + (size_t)(kstart + row) * 64 + col);
        }
        __syncthreads();

        float s[32];
#pragma unroll
        for (int j = 0; j < 32; j++) {
            float acc = 0.f;
#pragma unroll
            for (int d4 = 0; d4 < 16; d4++) {
                float4 kv = *(const float4*)&Ks[j][d4 * 4];
                acc += qreg[d4 * 4 + 0] * kv.x + qreg[d4 * 4 + 1] * kv.y +
                       qreg[d4 * 4 + 2] * kv.z + qreg[d4 * 4 + 3] * kv.w;
            }
            s[j] = (kstart + j <= qi) ? acc * 0.125f : -1e30f;
        }
        float mt = m;
#pragma unroll
        for (int j = 0; j < 32; j++) mt = fmaxf(mt, s[j]);
        float corr = expf(m - mt);
        m = mt;
        l *= corr;
#pragma unroll
        for (int d = 0; d < 64; d++) o[d] *= corr;
#pragma unroll
        for (int j = 0; j < 32; j++) {
            float p = expf(s[j] - m);
            l += p;
#pragma unroll
            for (int d4 = 0; d4 < 16; d4++) {
                float4 vv = *(const float4*)&Vs[j][d4 * 4];
                o[d4 * 4 + 0] += p * vv.x; o[d4 * 4 + 1] += p * vv.y;
                o[d4 * 4 + 2] += p * vv.z; o[d4 * 4 + 3] += p * vv.w;
            }
        }
    }
    float invl = 1.0f / l;
    float* op = Out + ((size_t)b * TSEQ + qi) * DMODEL + h * DHEAD;
#pragma unroll
    for (int d = 0; d < 64; d++) op[d] = o[d] * invl;
}

// ---------------------------------------------------------------------------
// Launch
// ---------------------------------------------------------------------------
extern "C" void kernel_launch(void* const* d_in, const int* in_sizes, int n_in,
                              void* d_out, int out_size) {
    const float* x     = (const float*)d_in[0];
    const int*   pos   = (const int*)d_in[1];
    const float* ln1   = (const float*)d_in[2];
    const float* ln2   = (const float*)d_in[3];
    const float* q_Us  = (const float*)d_in[4];
    const float* q_V   = (const float*)d_in[5];
    const float* k_Us  = (const float*)d_in[6];
    const float* k_V   = (const float*)d_in[7];
    const float* v_Us  = (const float*)d_in[8];
    const float* v_V   = (const float*)d_in[9];
    const float* o_Us  = (const float*)d_in[10];
    const float* o_V   = (const float*)d_in[11];
    const float* g_Us  = (const float*)d_in[12];
    const float* g_V   = (const float*)d_in[13];
    const float* u_Us  = (const float*)d_in[14];
    const float* u_V   = (const float*)d_in[15];
    const float* d_Us  = (const float*)d_in[16];
    const float* d_V   = (const float*)d_in[17];
    float* out = (float*)d_out;

    float* S = nullptr;
    cudaGetSymbolAddress((void**)&S, g_scratch);
    float* H  = S + OFF_H;     // 4,194,304 floats
    float* Bb = S + OFF_B;     // 4,718,592 floats
    float* C  = S + OFF_C;     // 6,291,456 floats

    float* hbuf  = H;
    float* wc    = C;                        // 2304x2048
    float* qkvr  = Bb;                       // 2048x2304
    float* qb    = C;                        // 2*32*1024*64   (wc dead)
    float* kb    = C + 4194304;              // 2*8*1024*64
    float* vb    = C + 5242880;              // 2*8*1024*64
    float* attn  = H;                        // 2048x2048      (hbuf dead)
    float* ar    = Bb;                       // 2048x1024      (qkvr dead)
    float* gr    = Bb;                       // 2048x1024      (ar dead)
    float* ur    = Bb + 2097152;             // 2048x1024
    float* inner = C;                        // 512x8192       (qb/kb/vb dead)
    float* part  = C + 4194304;              // 4 x 512x1024
    float* dr    = H;                        // 2048x1024      (hbuf dead)

    // ---- attention sub-block ----
    rms_kernel<<<NTOK, 256>>>(x, ln1, hbuf);
    concat_qkv<<<4608, 256>>>(q_V, k_V, v_V, wc);
    gemm128<0><<<dim3(18, 16), 256>>>(hbuf, wc, nullptr, qkvr, 2304, 2048, 2048);
    proj_kernel<<<dim3(TSEQ, NH, 2), 64>>>(qkvr, q_Us, pos, qb, NH, 1, 2304, 0);
    proj_kernel<<<dim3(TSEQ, NHK, 2), 64>>>(qkvr, k_Us, pos, kb, NHK, 1, 2304, 1536);
    proj_kernel<<<dim3(TSEQ, NHK, 2), 64>>>(qkvr, v_Us, pos, vb, NHK, 0, 2304, 1920);
    flash_kernel<<<dim3(8, 64), 128>>>(qb, kb, vb, attn);
    gemm128<0><<<dim3(8, 16), 256>>>(attn, o_V, nullptr, ar, 1024, 2048, 2048);
    gemm128<1><<<dim3(16, 16), 256>>>(ar, o_Us, x, out, 2048, 1024, 1024);

    // ---- MLP sub-block ----
    rms_kernel<<<NTOK, 256>>>(out, ln2, hbuf);
    gemm128<0><<<dim3(8, 16), 256>>>(hbuf, g_V, nullptr, gr, 1024, 2048, 2048);
    gemm128<0><<<dim3(8, 16), 256>>>(hbuf, u_V, nullptr, ur, 1024, 2048, 2048);

    for (int c = 0; c < NTOK / NCHUNK; c++) {
        const float* grc = gr + (size_t)c * NCHUNK * 1024;
        const float* urc = ur + (size_t)c * NCHUNK * 1024;
        gateup_kernel<<<dim3(128, 4), 256>>>(grc, urc, g_Us, u_Us, inner, 8192, 1024);
        gemm128<0><<<dim3(8, 4, 4), 256>>>(inner, d_V, nullptr, part, 1024, 8192, 2048);
        reduce4_kernel<<<512, 256>>>(part, dr + (size_t)c * NCHUNK * 1024);
    }
    gemm128<2><<<dim3(16, 16), 256>>>(dr, d_Us, nullptr, out, 2048, 1024, 1024);
}